// round 1
// baseline (speedup 1.0000x reference)
#include <cuda_runtime.h>

#define NV 256   // vertices
#define KD 16    // degree
#define HD 32    // hidden

// ---------------- scratch (static device globals; no allocation) ----------------
__device__ float g_F0[NV * KD * KD * 16];   // layer-1 input (broadcast X), 4 MB
__device__ float g_F1[NV * KD * KD * HD];   // layer-1 output, 8 MB
__device__ float g_Wc1[6 * 16 * HD];        // combined weight blocks, layer 1
__device__ float g_Wc2[6 * HD * HD];        // combined weight blocks, layer 2
__device__ signed char g_M[NV * KD * KD];   // per (n,t): map a -> p, or -1
__device__ float g_acc;                     // final scalar accumulator

// ---------------- map build: m[n][t][a] = p s.t. nbrs[nbrs[n,t]][p]==nbrs[n,a] ----------------
__global__ void build_maps(const int* __restrict__ nbrs) {
    int n = blockIdx.x;
    int tid = threadIdx.x;           // 256 = (t,a)
    int t = tid >> 4, a = tid & 15;
    int j = nbrs[n * KD + t];
    int target = nbrs[n * KD + a];
    int r = -1;
#pragma unroll
    for (int p = 0; p < KD; p++)
        if (nbrs[j * KD + p] == target) r = p;
    g_M[n * 256 + tid] = (signed char)r;
}

// ---------------- F0[n,p,q,c] = X[n,c]; also zero the scalar accumulator ----------------
__global__ void init_f0(const float* __restrict__ X) {
    int n = blockIdx.x, tid = threadIdx.x;   // tid = (p,q)
#pragma unroll
    for (int c = 0; c < 16; c++)
        g_F0[(n * 256 + tid) * 16 + c] = X[n * 16 + c];
    if (n == 0 && tid == 0) g_acc = 0.0f;
}

// ---------------- combined weight blocks ----------------
// Block semantics (A = I, S = k = 16, r = 1, tr = 16; c17/c18 are identically 0):
//   slot0 Wsb  = 16*W[0] + W[5] + 16*sum(W[6..14])   (multiplies sum_b)
//   slot1 W1b  = W[1]                                 (multiplies sum_ab, row-only)
//   slot2 W2b  = 16*W[2]                              (multiplies sum_t; 16 pre-folded)
//   slot3 W3b  = W[3]                                 (multiplies sum_tb, row-only)
//   slot4 W4b  = W[4]                                 (multiplies delta_ij * sum_all)
//   slot5 W15b = W[15]                                (multiplies diag gather T[n,t,e,e])
__global__ void prep_weights(const float* __restrict__ W1, const float* __restrict__ W2) {
    int l = blockIdx.x;
    int C = (l == 0) ? 16 : HD;
    const float* W = (l == 0) ? W1 : W2;
    float* O = (l == 0) ? g_Wc1 : g_Wc2;
    int tid = threadIdx.x;
    if (tid >= C * HD) return;
    int c = tid / HD, h = tid % HD;
    float wsb = 16.0f * W[(0 * C + c) * HD + h] + W[(5 * C + c) * HD + h];
    for (int m = 6; m < 15; m++) wsb += 16.0f * W[(m * C + c) * HD + h];
    O[(0 * C + c) * HD + h] = wsb;
    O[(1 * C + c) * HD + h] = W[(1 * C + c) * HD + h];
    O[(2 * C + c) * HD + h] = 16.0f * W[(2 * C + c) * HD + h];
    O[(3 * C + c) * HD + h] = W[(3 * C + c) * HD + h];
    O[(4 * C + c) * HD + h] = W[(4 * C + c) * HD + h];
    O[(5 * C + c) * HD + h] = W[(15 * C + c) * HD + h];
}

// ---------------- generic layer kernel: one CTA per vertex n, 256 threads = (i,j) ----------------
template <int C, bool FINAL>
__global__ __launch_bounds__(256, 1) void layer_kernel(const int* __restrict__ nbrs,
                                                       const float* __restrict__ bias,
                                                       const float* __restrict__ fcw) {
    constexpr int H = HD;
    const float* F  = (C == 16) ? g_F0 : g_F1;
    const float* Wc = (C == 16) ? g_Wc1 : g_Wc2;

    extern __shared__ float smem[];
    float* sG   = smem;                  // [16][16][C]  row sums G[t][p][c]
    float* sW   = sG + 256 * C;          // [6][C][H]
    float* sSAB = sW + 6 * C * H;        // [16][C] sum_ab
    float* sSTB = sSAB + 16 * C;         // [16][C] sum_tb
    float* sSAL = sSTB + 16 * C;         // [C]     sum_all
    float* sU   = sSAL + C;              // [16][H] row-only weighted term
    float* sD   = sU + 16 * H;           // [H]     delta-diagonal term
    float* sB   = sD + H;                // [H]     bias
    float* sFCW = sB + H;                // [H]     fc weights (FINAL only)
    float* sRED = sFCW + H;              // [256]   block reduce
    int* sNbr        = (int*)(sRED + 256);       // [16]
    unsigned* sQM    = (unsigned*)(sNbr + 16);   // [16] image bitmask
    signed char* sM  = (signed char*)(sQM + 16); // [16][16]

    int n = blockIdx.x;
    int tid = threadIdx.x;

    if (tid < 16) sNbr[tid] = nbrs[n * 16 + tid];
    sM[tid] = g_M[n * 256 + tid];
    for (int idx = tid; idx < 6 * C * H; idx += 256) sW[idx] = Wc[idx];
    if (tid < H) {
        sB[tid] = bias[tid];
        if (FINAL) sFCW[tid] = fcw[tid];
    }
    __syncthreads();

    if (tid < 16) {
        unsigned qm = 0;
#pragma unroll
        for (int a = 0; a < 16; a++) {
            int p = sM[tid * 16 + a];
            if (p >= 0) qm |= 1u << p;
        }
        sQM[tid] = qm;
    }
    __syncthreads();

    // ---- Phase G: G[t][p][c] = sum over valid q (image mask) of F[nbr[t], p, q, c]
    {
        int t = tid >> 4, p = tid & 15;
        unsigned qm = sQM[t];
        const float* base = F + (size_t)(sNbr[t] * 256 + p * 16) * C;
        float g[C];
#pragma unroll
        for (int c = 0; c < C; c++) g[c] = 0.0f;
#pragma unroll
        for (int q = 0; q < 16; q++) {
            if (qm & (1u << q)) {
                const float4* r = (const float4*)(base + q * C);
#pragma unroll
                for (int c4 = 0; c4 < C / 4; c4++) {
                    float4 v = r[c4];
                    g[c4 * 4 + 0] += v.x; g[c4 * 4 + 1] += v.y;
                    g[c4 * 4 + 2] += v.z; g[c4 * 4 + 3] += v.w;
                }
            }
        }
#pragma unroll
        for (int c = 0; c < C; c++) sG[(t * 16 + p) * C + c] = g[c];
    }
    __syncthreads();

    // ---- sum_ab[t][c] = sum over p in image of G[t][p][c]
    {
        int t = tid >> 4, ln = tid & 15;
        unsigned qm = sQM[t];
#pragma unroll
        for (int cc = 0; cc < C / 16; cc++) {
            int c = ln + cc * 16;
            float s = 0.0f;
#pragma unroll
            for (int p = 0; p < 16; p++)
                if (qm & (1u << p)) s += sG[(t * 16 + p) * C + c];
            sSAB[t * C + c] = s;
        }
    }
    __syncthreads();

    // ---- sum_tb[a][c] = sum_t valid * G[t][m_t[a]][c];  sum_all[c] = sum_t sum_ab[t][c]
    {
        int a = tid >> 4, ln = tid & 15;
#pragma unroll
        for (int cc = 0; cc < C / 16; cc++) {
            int c = ln + cc * 16;
            float s = 0.0f;
#pragma unroll
            for (int t = 0; t < 16; t++) {
                int p = sM[t * 16 + a];
                if (p >= 0) s += sG[(t * 16 + p) * C + c];
            }
            sSTB[a * C + c] = s;
        }
    }
    __syncthreads();
    if (tid < C) {
        float s = 0.0f;
#pragma unroll
        for (int t = 0; t < 16; t++) s += sSAB[t * C + tid];
        sSAL[tid] = s;
    }
    __syncthreads();

    // ---- row-only terms: U[i][h], D[h]
    {
#pragma unroll
        for (int rep = 0; rep < 2; rep++) {
            int idx = tid + rep * 256;     // 512 items (i,h)
            int i = idx >> 5, h = idx & 31;
            float u = 0.0f;
            for (int c = 0; c < C; c++)
                u += sSAB[i * C + c] * sW[(1 * C + c) * H + h]
                   + sSTB[i * C + c] * sW[(3 * C + c) * H + h];
            sU[i * H + h] = u;
        }
        if (tid < H) {
            float d = 0.0f;
            for (int c = 0; c < C; c++) d += sSAL[c] * sW[(4 * C + c) * H + tid];
            sD[tid] = d;
        }
    }
    __syncthreads();

    // ---- main: per (i,j) position
    {
        int i = tid >> 4, jd = tid & 15;
        float y[H];
#pragma unroll
        for (int h = 0; h < H; h++)
            y[h] = sU[i * H + h] + sB[h] + ((i == jd) ? sD[h] : 0.0f);

        // sum_t[i][j][c] accumulate across t (cross-neighbor gather)
        float st[C];
#pragma unroll
        for (int c = 0; c < C; c++) st[c] = 0.0f;
#pragma unroll
        for (int t = 0; t < 16; t++) {
            int pa = sM[t * 16 + i];
            int pb = sM[t * 16 + jd];
            if (pa >= 0 && pb >= 0) {
                const float4* r = (const float4*)(F + (size_t)(sNbr[t] * 256 + pa * 16 + pb) * C);
#pragma unroll
                for (int c4 = 0; c4 < C / 4; c4++) {
                    float4 v = r[c4];
                    st[c4 * 4 + 0] += v.x; st[c4 * 4 + 1] += v.y;
                    st[c4 * 4 + 2] += v.z; st[c4 * 4 + 3] += v.w;
                }
            }
        }

        const float* Wsb = sW + 0 * C * H;
        const float* W2b = sW + 2 * C * H;
        const float* W15 = sW + 5 * C * H;

        // st contribution
#pragma unroll 4
        for (int c = 0; c < C; c++) {
            float a1 = st[c];
            const float4* w1 = (const float4*)(W2b + c * H);
#pragma unroll
            for (int h4 = 0; h4 < H / 4; h4++) {
                float4 v1 = w1[h4];
                y[h4 * 4 + 0] += a1 * v1.x;
                y[h4 * 4 + 1] += a1 * v1.y;
                y[h4 * 4 + 2] += a1 * v1.z;
                y[h4 * 4 + 3] += a1 * v1.w;
            }
        }

        // sum_b + diag contributions (only when (i,j) is valid)
        int mij = sM[i * 16 + jd];
        if (mij >= 0) {
            const float* grow = &sG[(i * 16 + mij) * C];
            const float4* drow = (const float4*)(F + (size_t)(sNbr[i] * 256 + mij * 16 + mij) * C);
#pragma unroll
            for (int c4 = 0; c4 < C / 4; c4++) {
                float4 dv = drow[c4];
                float dgv[4] = {dv.x, dv.y, dv.z, dv.w};
#pragma unroll
                for (int cl = 0; cl < 4; cl++) {
                    int c = c4 * 4 + cl;
                    float a0 = grow[c];
                    float a2 = dgv[cl];
                    const float4* w0 = (const float4*)(Wsb + c * H);
                    const float4* w2 = (const float4*)(W15 + c * H);
#pragma unroll
                    for (int h4 = 0; h4 < H / 4; h4++) {
                        float4 v0 = w0[h4], v2 = w2[h4];
                        y[h4 * 4 + 0] += a0 * v0.x + a2 * v2.x;
                        y[h4 * 4 + 1] += a0 * v0.y + a2 * v2.y;
                        y[h4 * 4 + 2] += a0 * v0.z + a2 * v2.z;
                        y[h4 * 4 + 3] += a0 * v0.w + a2 * v2.w;
                    }
                }
            }
        }

        if (FINAL) {
            float loc = 0.0f;
#pragma unroll
            for (int h = 0; h < H; h++) loc += fmaxf(y[h], 0.0f) * sFCW[h];
            sRED[tid] = loc;
            __syncthreads();
            for (int s = 128; s > 0; s >>= 1) {
                if (tid < s) sRED[tid] += sRED[tid + s];
                __syncthreads();
            }
            if (tid == 0) atomicAdd(&g_acc, sRED[0]);
        } else {
            float* o = g_F1 + (size_t)(n * 256 + tid) * H;
#pragma unroll
            for (int h = 0; h < H; h++) o[h] = fmaxf(y[h], 0.0f);
        }
    }
}

__global__ void finish(const float* __restrict__ fcb, float* __restrict__ out) {
    out[0] = g_acc + fcb[0];
}

// smem bytes for layer kernel
static int layer_smem_bytes(int C) {
    int floats = 256 * C + 6 * C * HD + 16 * C + 16 * C + C + 16 * HD + HD + HD + HD + 256;
    return floats * 4 + 16 * 4 + 16 * 4 + 256;
}

extern "C" void kernel_launch(void* const* d_in, const int* in_sizes, int n_in,
                              void* d_out, int out_size) {
    const float* X   = (const float*)d_in[0];
    const int*   nbr = (const int*)d_in[1];
    const float* W1  = (const float*)d_in[2];
    const float* b1  = (const float*)d_in[3];
    const float* W2  = (const float*)d_in[4];
    const float* b2  = (const float*)d_in[5];
    const float* fcw = (const float*)d_in[6];
    const float* fcb = (const float*)d_in[7];
    float* out = (float*)d_out;

    int sm1 = layer_smem_bytes(16);
    int sm2 = layer_smem_bytes(32);
    cudaFuncSetAttribute(layer_kernel<16, false>, cudaFuncAttributeMaxDynamicSharedMemorySize, sm1);
    cudaFuncSetAttribute(layer_kernel<32, true>, cudaFuncAttributeMaxDynamicSharedMemorySize, sm2);

    build_maps<<<NV, 256>>>(nbr);
    init_f0<<<NV, 256>>>(X);
    prep_weights<<<2, 1024>>>(W1, W2);
    layer_kernel<16, false><<<NV, 256, sm1>>>(nbr, b1, nullptr);
    layer_kernel<32, true><<<NV, 256, sm2>>>(nbr, b2, fcw);
    finish<<<1, 1>>>(fcb, out);
}

// round 2
// speedup vs baseline: 1.5580x; 1.5580x over previous
#include <cuda_runtime.h>

#define NV 256   // vertices
#define KD 16    // degree
#define HD 32    // hidden

// ---------------- scratch ----------------
__device__ float g_F1[NV * 256 * HD];       // layer-1 output, 8 MB
__device__ float g_Wc1[6 * 16 * HD];        // combined weight blocks, layer 1
__device__ float g_Wc2[6 * HD * HD];        // combined weight blocks, layer 2
__device__ signed char g_M[NV * 256];       // per (n,t): map a -> p, or -1
__device__ float g_acc;                     // final scalar accumulator

typedef unsigned long long ull;

// ---------------- packed f32x2 helpers ----------------
__device__ __forceinline__ ull pack2(float x) {
    ull r; asm("mov.b64 %0, {%1, %1};" : "=l"(r) : "f"(x)); return r;
}
__device__ __forceinline__ ull pack2f(float lo, float hi) {
    ull r; asm("mov.b64 %0, {%1, %2};" : "=l"(r) : "f"(lo), "f"(hi)); return r;
}
__device__ __forceinline__ void unpack2(ull v, float& lo, float& hi) {
    asm("mov.b64 {%0, %1}, %2;" : "=f"(lo), "=f"(hi) : "l"(v));
}
__device__ __forceinline__ void dfma(ull& acc, ull a, ull b) {
    asm("fma.rn.f32x2 %0, %1, %2, %0;" : "+l"(acc) : "l"(a), "l"(b));
}
// y[0..15] (h pairs) += a2 * wrow[0..31]
__device__ __forceinline__ void gemm_row(ull* y, ull a, const float* wrow) {
    const longlong2* w = (const longlong2*)wrow;
#pragma unroll
    for (int k8 = 0; k8 < 8; k8++) {
        longlong2 v = w[k8];
        dfma(y[2 * k8 + 0], a, (ull)v.x);
        dfma(y[2 * k8 + 1], a, (ull)v.y);
    }
}
__device__ __forceinline__ void cp16(float* sdst, const float4* gsrc) {
    unsigned s = (unsigned)__cvta_generic_to_shared(sdst);
    asm volatile("cp.async.cg.shared.global [%0], [%1], 16;" :: "r"(s), "l"(gsrc));
}
// swizzled tile element (tile rows 32 floats, float4-level XOR swizzle)
__device__ __forceinline__ float tileElem(const float* buf, int r, int c) {
    return buf[r * 32 + (((c >> 2) ^ (r & 7)) << 2) + (c & 3)];
}

// ---------------- map build + zero acc ----------------
__global__ void build_maps(const int* __restrict__ nbrs) {
    int n = blockIdx.x, tid = threadIdx.x;
    int t = tid >> 4, a = tid & 15;
    int jv = nbrs[n * KD + t];
    int target = nbrs[n * KD + a];
    int r = -1;
#pragma unroll
    for (int p = 0; p < KD; p++)
        if (nbrs[jv * KD + p] == target) r = p;
    g_M[n * 256 + tid] = (signed char)r;
    if (n == 0 && tid == 0) g_acc = 0.0f;
}

// ---------------- combined weight blocks (A = I: S=16, r=1, tr=16; c17/c18 = 0) ----------------
// slot0 Wsb = 16*W[0] + W[5] + 16*sum(W[6..14]); slot1 = W[1]; slot2 = 16*W[2];
// slot3 = W[3]; slot4 = W[4]; slot5 = W[15]
__global__ void prep_weights(const float* __restrict__ W1, const float* __restrict__ W2) {
    int l = blockIdx.x;
    int C = (l == 0) ? 16 : HD;
    const float* W = (l == 0) ? W1 : W2;
    float* O = (l == 0) ? g_Wc1 : g_Wc2;
    int tid = threadIdx.x;
    if (tid >= C * HD) return;
    int c = tid / HD, h = tid % HD;
    float wsb = 16.0f * W[(0 * C + c) * HD + h] + W[(5 * C + c) * HD + h];
    for (int m = 6; m < 15; m++) wsb += 16.0f * W[(m * C + c) * HD + h];
    O[(0 * C + c) * HD + h] = wsb;
    O[(1 * C + c) * HD + h] = W[(1 * C + c) * HD + h];
    O[(2 * C + c) * HD + h] = 16.0f * W[(2 * C + c) * HD + h];
    O[(3 * C + c) * HD + h] = W[(3 * C + c) * HD + h];
    O[(4 * C + c) * HD + h] = W[(4 * C + c) * HD + h];
    O[(5 * C + c) * HD + h] = W[(15 * C + c) * HD + h];
}

// ================= layer 1 (specialized: F0[n,p,q,c] = X[n,c], no gathers) =================
__global__ __launch_bounds__(256) void layer1_kernel(const int* __restrict__ nbrs,
                                                     const float* __restrict__ X,
                                                     const float* __restrict__ b1) {
    __shared__ float sXn[16 * 16];        // X of the 16 neighbors
    __shared__ float sW[6 * 16 * HD];     // 3072 floats
    __shared__ float sSAB[16 * 16];
    __shared__ float sSTB[16 * 16];
    __shared__ float sSAL[16];
    __shared__ float sU[16 * HD];
    __shared__ float sD[HD];
    __shared__ float sB[HD];
    __shared__ float sCnt[16];
    __shared__ unsigned sVM[16];
    __shared__ signed char sM[256];

    int n = blockIdx.x, tid = threadIdx.x;
    int i = tid >> 4, j = tid & 15;

    sM[tid] = g_M[n * 256 + tid];
    sXn[tid] = X[nbrs[n * 16 + i] * 16 + j];      // row i = neighbor t=i, col j = channel
    for (int idx = tid; idx < 6 * 16 * HD; idx += 256) sW[idx] = g_Wc1[idx];
    if (tid < HD) sB[tid] = b1[tid];
    __syncthreads();

    if (tid < 16) {
        unsigned vm = 0;
#pragma unroll
        for (int a = 0; a < 16; a++)
            if (sM[tid * 16 + a] >= 0) vm |= 1u << a;
        sVM[tid] = vm;
        sCnt[tid] = (float)__popc(vm);
    }
    __syncthreads();

    // sum_ab[t][c] = cnt_t^2 * Xn[t][c]   (t=i, c=j per thread)
    sSAB[tid] = sCnt[i] * sCnt[i] * sXn[tid];
    // sum_tb[a][c] = sum_t valid(t,a) * cnt_t * Xn[t][c]
    {
        float s = 0.0f;
#pragma unroll
        for (int t = 0; t < 16; t++)
            if ((sVM[t] >> i) & 1) s += sCnt[t] * sXn[t * 16 + j];
        sSTB[tid] = s;
    }
    __syncthreads();
    if (tid < 16) {
        float s = 0.0f;
#pragma unroll
        for (int t = 0; t < 16; t++) s += sSAB[t * 16 + tid];
        sSAL[tid] = s;
    }
    __syncthreads();
    {   // U[i][h], D[h]
        int r0 = tid >> 5, h = tid & 31;
        float ua = 0.0f, ub = 0.0f;
#pragma unroll
        for (int c = 0; c < 16; c++) {
            float w1b = sW[1 * 512 + c * 32 + h];
            float w3b = sW[3 * 512 + c * 32 + h];
            ua += sSAB[r0 * 16 + c] * w1b + sSTB[r0 * 16 + c] * w3b;
            ub += sSAB[(r0 + 8) * 16 + c] * w1b + sSTB[(r0 + 8) * 16 + c] * w3b;
        }
        sU[r0 * 32 + h] = ua;
        sU[(r0 + 8) * 32 + h] = ub;
    }
    if (tid < HD) {
        float s = 0.0f;
#pragma unroll
        for (int c = 0; c < 16; c++) s += sSAL[c] * sW[4 * 512 + c * 32 + tid];
        sD[tid] = s;
    }
    __syncthreads();

    // st[c] = sum_t valid(t,i)&valid(t,j) * Xn[t][c]
    float st[16];
#pragma unroll
    for (int c = 0; c < 16; c++) st[c] = 0.0f;
#pragma unroll
    for (int t = 0; t < 16; t++) {
        unsigned vm = sVM[t];
        if (((vm >> i) & (vm >> j)) & 1) {
            const float4* xr = (const float4*)(sXn + t * 16);
#pragma unroll
            for (int c4 = 0; c4 < 4; c4++) {
                float4 v = xr[c4];
                st[c4 * 4 + 0] += v.x; st[c4 * 4 + 1] += v.y;
                st[c4 * 4 + 2] += v.z; st[c4 * 4 + 3] += v.w;
            }
        }
    }

    // y = U + b + delta*D + st@W2b + valid * Xn_i @ (cnt_i*Wsb + W15)
    ull y[16];
#pragma unroll
    for (int k = 0; k < 16; k++) {
        int h0 = 2 * k, h1 = 2 * k + 1;
        float lo = sU[i * 32 + h0] + sB[h0] + ((i == j) ? sD[h0] : 0.0f);
        float hi = sU[i * 32 + h1] + sB[h1] + ((i == j) ? sD[h1] : 0.0f);
        y[k] = pack2f(lo, hi);
    }
    bool val = (sM[tid] >= 0);
    float cnti = sCnt[i];
#pragma unroll
    for (int c = 0; c < 16; c++) {
        float xv = val ? sXn[i * 16 + c] : 0.0f;
        gemm_row(y, pack2(st[c]), sW + 2 * 512 + c * 32);
        gemm_row(y, pack2(cnti * xv), sW + 0 * 512 + c * 32);
        gemm_row(y, pack2(xv), sW + 5 * 512 + c * 32);
    }
    // relu + store F1 row
    float* dst = g_F1 + (size_t)(n * 256 + tid) * 32;
#pragma unroll
    for (int q = 0; q < 8; q++) {
        float4 o;
        unpack2(y[2 * q + 0], o.x, o.y);
        unpack2(y[2 * q + 1], o.z, o.w);
        o.x = fmaxf(o.x, 0.0f); o.y = fmaxf(o.y, 0.0f);
        o.z = fmaxf(o.z, 0.0f); o.w = fmaxf(o.w, 0.0f);
        ((float4*)dst)[q] = o;
    }
}

// ================= layer 2 (staged smem tiles, cp.async double-buffer, fused final sum) =================
__device__ __forceinline__ void issue_tile(int t, float* buf, int tid, const int* sNbr) {
    const float4* src = (const float4*)(g_F1 + (size_t)sNbr[t] * 8192);
#pragma unroll
    for (int k = 0; k < 8; k++) {
        int g = k * 256 + tid;      // float4 index, coalesced
        int r = g >> 3, c4 = g & 7;
        cp16(buf + r * 32 + ((c4 ^ (r & 7)) << 2), src + g);
    }
    asm volatile("cp.async.commit_group;");
}

#define SMEM2_FLOATS (6144 + 8192 + 8192 + 528 + 512 + 512 + 32 + 512 + 32 + 32 + 32 + 256)
#define SMEM2_BYTES (SMEM2_FLOATS * 4 + 16 * 4 + 16 * 4 + 256)

__global__ __launch_bounds__(256, 2) void layer2_kernel(const int* __restrict__ nbrs,
                                                        const float* __restrict__ b2,
                                                        const float* __restrict__ fcw) {
    extern __shared__ float smem[];
    float* sW    = smem;                 // [6][32][32]
    float* tile0 = sW + 6144;            // [256][32] swizzled
    float* tile1 = tile0 + 8192;
    float* sGt   = tile1 + 8192;         // [16][33] padded
    float* sSAB  = sGt + 528;            // [16][32]
    float* sSTB  = sSAB + 512;           // [16][32]
    float* sSAL  = sSTB + 512;           // [32]
    float* sU    = sSAL + 32;            // [16][32]
    float* sD    = sU + 512;             // [32]
    float* sB    = sD + 32;              // [32]
    float* sFCW  = sB + 32;              // [32]
    float* sRED  = sFCW + 32;            // [256]
    int* sNbr    = (int*)(sRED + 256);   // [16]
    unsigned* sQM = (unsigned*)(sNbr + 16);  // [16] image bitmask (bits p)
    signed char* sM = (signed char*)(sQM + 16); // [16][16]

    int n = blockIdx.x, tid = threadIdx.x;
    int i = tid >> 4, j = tid & 15;
    int a0 = tid >> 5, ccol = tid & 31;  // mapping for Gt/stb/U (rows a0, a0+8)

    sM[tid] = g_M[n * 256 + tid];
    if (tid < 16) sNbr[tid] = nbrs[n * 16 + tid];
    for (int idx = tid; idx < 6144; idx += 256) sW[idx] = g_Wc2[idx];
    if (tid < 32) { sB[tid] = b2[tid]; sFCW[tid] = fcw[tid]; }
    __syncthreads();
    if (tid < 16) {
        unsigned qm = 0;
#pragma unroll
        for (int a = 0; a < 16; a++) {
            int p = sM[tid * 16 + a];
            if (p >= 0) qm |= 1u << p;
        }
        sQM[tid] = qm;
    }
    __syncthreads();

    issue_tile(0, tile0, tid, sNbr);

    int mij = sM[i * 16 + j];
    float st[32];
#pragma unroll
    for (int c = 0; c < 32; c++) st[c] = 0.0f;
    ull y[16];
#pragma unroll
    for (int k = 0; k < 16; k++) y[k] = 0ull;
    float stb0 = 0.0f, stb1 = 0.0f;

    for (int t = 0; t < 16; t++) {
        float* buf = (t & 1) ? tile1 : tile0;
        if (t < 15) {
            issue_tile(t + 1, (t & 1) ? tile0 : tile1, tid, sNbr);
            asm volatile("cp.async.wait_group 1;");
        } else {
            asm volatile("cp.async.wait_group 0;");
        }
        __syncthreads();   // tile t ready in all threads

        // phase A: Gt[p][c] = sum over q in image of tile[p*16+q][c]
        {
            unsigned qm = sQM[t];
            float g0 = 0.0f, g1 = 0.0f;
            int r0 = a0 * 16, r1 = (a0 + 8) * 16;
#pragma unroll
            for (int q = 0; q < 16; q++) {
                if (qm & (1u << q)) {
                    g0 += tileElem(buf, r0 + q, ccol);
                    g1 += tileElem(buf, r1 + q, ccol);
                }
            }
            sGt[a0 * 33 + ccol] = g0;
            sGt[(a0 + 8) * 33 + ccol] = g1;
        }
        // phase A2: st accumulation (per (i,j) gather from smem tile)
        {
            int pa = sM[t * 16 + i], pb = sM[t * 16 + j];
            if ((pa | pb) >= 0) {
                int r = pa * 16 + pb;
                const float4* tb = (const float4*)buf;
#pragma unroll
                for (int c4 = 0; c4 < 8; c4++) {
                    float4 v = tb[r * 8 + (c4 ^ (r & 7))];
                    st[c4 * 4 + 0] += v.x; st[c4 * 4 + 1] += v.y;
                    st[c4 * 4 + 2] += v.z; st[c4 * 4 + 3] += v.w;
                }
            }
        }
        __syncthreads();   // sGt ready

        // phase B: sum_tb accumulation (register-owned)
        {
            int p0 = sM[t * 16 + a0], p1 = sM[t * 16 + a0 + 8];
            if (p0 >= 0) stb0 += sGt[p0 * 33 + ccol];
            if (p1 >= 0) stb1 += sGt[p1 * 33 + ccol];
        }
        // sum_ab[t][c]
        if (tid < 32) {
            unsigned qm = sQM[t];
            float s = 0.0f;
#pragma unroll
            for (int p = 0; p < 16; p++)
                if ((qm >> p) & 1) s += sGt[p * 33 + tid];
            sSAB[t * 32 + tid] = s;
        }
        // gb/dg contributions for threads whose i == t (rows in image)
        if (t == i && mij >= 0) {
            int rd = mij * 17;  // diagonal element row mij, col mij
#pragma unroll
            for (int c = 0; c < 32; c++) {
                gemm_row(y, pack2(sGt[mij * 33 + c]), sW + 0 * 1024 + c * 32);   // Wsb
                gemm_row(y, pack2(tileElem(buf, rd, c)), sW + 5 * 1024 + c * 32); // W15
            }
        }
        __syncthreads();   // all reads of tile/sGt done before next iteration writes
    }

    sSTB[a0 * 32 + ccol] = stb0;
    sSTB[(a0 + 8) * 32 + ccol] = stb1;
    __syncthreads();
    if (tid < 32) {
        float s = 0.0f;
#pragma unroll
        for (int t = 0; t < 16; t++) s += sSAB[t * 32 + tid];
        sSAL[tid] = s;
    }
    __syncthreads();
    {   // U[i][h]
        float ua = 0.0f, ub = 0.0f;
#pragma unroll
        for (int c = 0; c < 32; c++) {
            float w1b = sW[1 * 1024 + c * 32 + ccol];
            float w3b = sW[3 * 1024 + c * 32 + ccol];
            ua += sSAB[a0 * 32 + c] * w1b + sSTB[a0 * 32 + c] * w3b;
            ub += sSAB[(a0 + 8) * 32 + c] * w1b + sSTB[(a0 + 8) * 32 + c] * w3b;
        }
        sU[a0 * 32 + ccol] = ua;
        sU[(a0 + 8) * 32 + ccol] = ub;
    }
    if (tid < 32) {
        float s = 0.0f;
#pragma unroll
        for (int c = 0; c < 32; c++) s += sSAL[c] * sW[4 * 1024 + c * 32 + tid];
        sD[tid] = s;
    }
    __syncthreads();

    // st GEMM (W2b)
#pragma unroll
    for (int c = 0; c < 32; c++)
        gemm_row(y, pack2(st[c]), sW + 2 * 1024 + c * 32);

    // finish: add U/D/bias, relu, dot with fc weights, block-reduce
    float loc = 0.0f;
#pragma unroll
    for (int k = 0; k < 16; k++) {
        float lo, hi;
        unpack2(y[k], lo, hi);
        int h0 = 2 * k, h1 = 2 * k + 1;
        float v0 = lo + sU[i * 32 + h0] + sB[h0] + ((i == j) ? sD[h0] : 0.0f);
        float v1 = hi + sU[i * 32 + h1] + sB[h1] + ((i == j) ? sD[h1] : 0.0f);
        loc += fmaxf(v0, 0.0f) * sFCW[h0] + fmaxf(v1, 0.0f) * sFCW[h1];
    }
    sRED[tid] = loc;
    __syncthreads();
#pragma unroll
    for (int s = 128; s > 0; s >>= 1) {
        if (tid < s) sRED[tid] += sRED[tid + s];
        __syncthreads();
    }
    if (tid == 0) atomicAdd(&g_acc, sRED[0]);
}

__global__ void finish(const float* __restrict__ fcb, float* __restrict__ out) {
    out[0] = g_acc + fcb[0];
}

extern "C" void kernel_launch(void* const* d_in, const int* in_sizes, int n_in,
                              void* d_out, int out_size) {
    const float* X   = (const float*)d_in[0];
    const int*   nbr = (const int*)d_in[1];
    const float* W1  = (const float*)d_in[2];
    const float* b1  = (const float*)d_in[3];
    const float* W2  = (const float*)d_in[4];
    const float* b2  = (const float*)d_in[5];
    const float* fcw = (const float*)d_in[6];
    const float* fcb = (const float*)d_in[7];
    float* out = (float*)d_out;

    cudaFuncSetAttribute(layer2_kernel, cudaFuncAttributeMaxDynamicSharedMemorySize, SMEM2_BYTES);

    build_maps<<<NV, 256>>>(nbr);
    prep_weights<<<2, 1024>>>(W1, W2);
    layer1_kernel<<<NV, 256>>>(nbr, X, b1);
    layer2_kernel<<<NV, 256, SMEM2_BYTES>>>(nbr, b2, fcw);
    finish<<<1, 1>>>(fcb, out);
}

// round 3
// speedup vs baseline: 1.9396x; 1.2449x over previous
#include <cuda_runtime.h>

#define NV 256   // vertices
#define KD 16    // degree
#define HD 32    // hidden

// ---------------- scratch ----------------
__device__ float g_F1[NV * 256 * HD];       // layer-1 output, 8 MB
__device__ float g_Wc1[6 * 16 * HD];        // combined weight blocks, layer 1
__device__ float g_Wc2[6 * HD * HD];        // combined weight blocks, layer 2
__device__ signed char g_M[NV * 256];       // per (n,t): map a -> p, or -1
__device__ float g_acc;                     // final scalar accumulator

typedef unsigned long long ull;

// ---------------- packed f32x2 helpers ----------------
__device__ __forceinline__ ull pack2(float x) {
    ull r; asm("mov.b64 %0, {%1, %1};" : "=l"(r) : "f"(x)); return r;
}
__device__ __forceinline__ ull pack2f(float lo, float hi) {
    ull r; asm("mov.b64 %0, {%1, %2};" : "=l"(r) : "f"(lo), "f"(hi)); return r;
}
__device__ __forceinline__ void unpack2(ull v, float& lo, float& hi) {
    asm("mov.b64 {%0, %1}, %2;" : "=f"(lo), "=f"(hi) : "l"(v));
}
__device__ __forceinline__ void dfma(ull& acc, ull a, ull b) {
    asm("fma.rn.f32x2 %0, %1, %2, %0;" : "+l"(acc) : "l"(a), "l"(b));
}
__device__ __forceinline__ ull addx2(ull a, ull b) {
    ull r; asm("add.rn.f32x2 %0, %1, %2;" : "=l"(r) : "l"(a), "l"(b)); return r;
}
// y[0..15] (h pairs) += a2 * wrow[0..31]
__device__ __forceinline__ void gemm_row(ull* y, ull a, const float* wrow) {
    const longlong2* w = (const longlong2*)wrow;
#pragma unroll
    for (int k8 = 0; k8 < 8; k8++) {
        longlong2 v = w[k8];
        dfma(y[2 * k8 + 0], a, (ull)v.x);
        dfma(y[2 * k8 + 1], a, (ull)v.y);
    }
}
__device__ __forceinline__ void cp16(float* sdst, const float4* gsrc) {
    unsigned s = (unsigned)__cvta_generic_to_shared(sdst);
    asm volatile("cp.async.cg.shared.global [%0], [%1], 16;" :: "r"(s), "l"(gsrc));
}
// swizzled tile element (tile rows 32 floats, float4-level XOR swizzle)
__device__ __forceinline__ float tileElem(const float* buf, int r, int c) {
    return buf[r * 32 + (((c >> 2) ^ (r & 7)) << 2) + (c & 3)];
}

// ---------------- setup: maps (blocks 0..255) + combined weights (blocks 256,257) ----------------
// Weight block semantics (A = I: S=16, r=1, tr=16; c17/c18 identically 0):
// slot0 Wsb = 16*W[0] + W[5] + 16*sum(W[6..14]); slot1 = W[1]; slot2 = 16*W[2];
// slot3 = W[3]; slot4 = W[4]; slot5 = W[15]
__global__ void setup_kernel(const int* __restrict__ nbrs,
                             const float* __restrict__ W1,
                             const float* __restrict__ W2) {
    int b = blockIdx.x, tid = threadIdx.x;
    if (b < 256) {
        int t = tid >> 4, a = tid & 15;
        int jv = nbrs[b * KD + t];
        int target = nbrs[b * KD + a];
        int r = -1;
#pragma unroll
        for (int p = 0; p < KD; p++)
            if (nbrs[jv * KD + p] == target) r = p;
        g_M[b * 256 + tid] = (signed char)r;
        if (b == 0 && tid == 0) g_acc = 0.0f;
    } else {
        int l = b - 256;
        int C = (l == 0) ? 16 : HD;
        const float* W = (l == 0) ? W1 : W2;
        float* O = (l == 0) ? g_Wc1 : g_Wc2;
        for (int idx = tid; idx < C * HD; idx += 256) {
            int c = idx / HD, h = idx % HD;
            float wsb = 16.0f * W[(0 * C + c) * HD + h] + W[(5 * C + c) * HD + h];
            for (int m = 6; m < 15; m++) wsb += 16.0f * W[(m * C + c) * HD + h];
            O[(0 * C + c) * HD + h] = wsb;
            O[(1 * C + c) * HD + h] = W[(1 * C + c) * HD + h];
            O[(2 * C + c) * HD + h] = 16.0f * W[(2 * C + c) * HD + h];
            O[(3 * C + c) * HD + h] = W[(3 * C + c) * HD + h];
            O[(4 * C + c) * HD + h] = W[(4 * C + c) * HD + h];
            O[(5 * C + c) * HD + h] = W[(15 * C + c) * HD + h];
        }
    }
}

// ================= layer 1 (specialized: F0[n,p,q,c] = X[n,c], no gathers) =================
__global__ __launch_bounds__(256) void layer1_kernel(const int* __restrict__ nbrs,
                                                     const float* __restrict__ X,
                                                     const float* __restrict__ b1) {
    __shared__ float sXn[16 * 16];
    __shared__ float sW[6 * 16 * HD];
    __shared__ float sSAB[16 * 16];
    __shared__ float sSTB[16 * 16];
    __shared__ float sSAL[16];
    __shared__ float sU[16 * HD];
    __shared__ float sD[HD];
    __shared__ float sB[HD];
    __shared__ float sCnt[16];
    __shared__ unsigned sVM[16];
    __shared__ signed char sM[256];

    int n = blockIdx.x, tid = threadIdx.x;
    int i = tid >> 4, j = tid & 15;

    sM[tid] = g_M[n * 256 + tid];
    sXn[tid] = X[nbrs[n * 16 + i] * 16 + j];
    for (int idx = tid; idx < 6 * 16 * HD; idx += 256) sW[idx] = g_Wc1[idx];
    if (tid < HD) sB[tid] = b1[tid];
    __syncthreads();

    if (tid < 16) {
        unsigned vm = 0;
#pragma unroll
        for (int a = 0; a < 16; a++)
            if (sM[tid * 16 + a] >= 0) vm |= 1u << a;
        sVM[tid] = vm;
        sCnt[tid] = (float)__popc(vm);
    }
    __syncthreads();

    sSAB[tid] = sCnt[i] * sCnt[i] * sXn[tid];
    {
        float s = 0.0f;
#pragma unroll
        for (int t = 0; t < 16; t++)
            if ((sVM[t] >> i) & 1) s += sCnt[t] * sXn[t * 16 + j];
        sSTB[tid] = s;
    }
    __syncthreads();
    if (tid < 16) {
        float s = 0.0f;
#pragma unroll
        for (int t = 0; t < 16; t++) s += sSAB[t * 16 + tid];
        sSAL[tid] = s;
    }
    __syncthreads();
    {
        int r0 = tid >> 5, h = tid & 31;
        float ua = 0.0f, ub = 0.0f;
#pragma unroll
        for (int c = 0; c < 16; c++) {
            float w1b = sW[1 * 512 + c * 32 + h];
            float w3b = sW[3 * 512 + c * 32 + h];
            ua += sSAB[r0 * 16 + c] * w1b + sSTB[r0 * 16 + c] * w3b;
            ub += sSAB[(r0 + 8) * 16 + c] * w1b + sSTB[(r0 + 8) * 16 + c] * w3b;
        }
        sU[r0 * 32 + h] = ua;
        sU[(r0 + 8) * 32 + h] = ub;
    }
    if (tid < HD) {
        float s = 0.0f;
#pragma unroll
        for (int c = 0; c < 16; c++) s += sSAL[c] * sW[4 * 512 + c * 32 + tid];
        sD[tid] = s;
    }
    __syncthreads();

    float st[16];
#pragma unroll
    for (int c = 0; c < 16; c++) st[c] = 0.0f;
#pragma unroll
    for (int t = 0; t < 16; t++) {
        unsigned vm = sVM[t];
        if (((vm >> i) & (vm >> j)) & 1) {
            const float4* xr = (const float4*)(sXn + t * 16);
#pragma unroll
            for (int c4 = 0; c4 < 4; c4++) {
                float4 v = xr[c4];
                st[c4 * 4 + 0] += v.x; st[c4 * 4 + 1] += v.y;
                st[c4 * 4 + 2] += v.z; st[c4 * 4 + 3] += v.w;
            }
        }
    }

    ull y[16];
#pragma unroll
    for (int k = 0; k < 16; k++) {
        int h0 = 2 * k, h1 = 2 * k + 1;
        float lo = sU[i * 32 + h0] + sB[h0] + ((i == j) ? sD[h0] : 0.0f);
        float hi = sU[i * 32 + h1] + sB[h1] + ((i == j) ? sD[h1] : 0.0f);
        y[k] = pack2f(lo, hi);
    }
    bool val = (sM[tid] >= 0);
    float cnti = sCnt[i];
#pragma unroll
    for (int c = 0; c < 16; c++) {
        float xv = val ? sXn[i * 16 + c] : 0.0f;
        gemm_row(y, pack2(st[c]), sW + 2 * 512 + c * 32);
        gemm_row(y, pack2(cnti * xv), sW + 0 * 512 + c * 32);
        gemm_row(y, pack2(xv), sW + 5 * 512 + c * 32);
    }
    float* dst = g_F1 + (size_t)(n * 256 + tid) * 32;
#pragma unroll
    for (int q = 0; q < 8; q++) {
        float4 o;
        unpack2(y[2 * q + 0], o.x, o.y);
        unpack2(y[2 * q + 1], o.z, o.w);
        o.x = fmaxf(o.x, 0.0f); o.y = fmaxf(o.y, 0.0f);
        o.z = fmaxf(o.z, 0.0f); o.w = fmaxf(o.w, 0.0f);
        ((float4*)dst)[q] = o;
    }
}

// ================= layer 2 =================
__device__ __forceinline__ void issue_tile(int t, float* buf, int tid, const int* sNbr) {
    const float4* src = (const float4*)(g_F1 + (size_t)sNbr[t] * 8192);
#pragma unroll
    for (int k = 0; k < 8; k++) {
        int g = k * 256 + tid;
        int r = g >> 3, c4 = g & 7;
        cp16(buf + r * 32 + ((c4 ^ (r & 7)) << 2), src + g);
    }
    asm volatile("cp.async.commit_group;");
}

// smem floats: sW 6144 | tile0 8192 | tile1 8192 | sGt 528 | sSAB 512 | sSTB 512 |
//              sSAL 32 | sU 512 | sD 32 | sB 32 | sFCW 32 | sRED 256 | sYB 544
#define SMEM2_FLOATS (6144 + 8192 + 8192 + 528 + 512 + 512 + 32 + 512 + 32 + 32 + 32 + 256 + 544)
#define SMEM2_BYTES (SMEM2_FLOATS * 4 + 16 * 4 + 16 * 4 + 256 + 64)

__global__ __launch_bounds__(256, 2) void layer2_kernel(const int* __restrict__ nbrs,
                                                        const float* __restrict__ b2,
                                                        const float* __restrict__ fcw) {
    extern __shared__ float smem[];
    float* sW    = smem;                 // [6][32][32]
    float* tile0 = sW + 6144;            // [256][32] swizzled
    float* tile1 = tile0 + 8192;
    float* sGt   = tile1 + 8192;         // [16][33] a-indexed G' (validity-masked)
    float* sSAB  = sGt + 528;            // [16][32]
    float* sSTB  = sSAB + 512;           // [16][32]
    float* sSAL  = sSTB + 512;           // [32]
    float* sU    = sSAL + 32;            // [16][32]
    float* sD    = sU + 512;             // [32]
    float* sB    = sD + 32;              // [32]
    float* sFCW  = sB + 32;              // [32]
    float* sRED  = sFCW + 32;            // [256]
    float* sYB   = sRED + 256;           // [16][17] ull-padded collab gemm output
    int* sNbr    = (int*)(sYB + 544);    // [16]
    unsigned* sQM = (unsigned*)(sNbr + 16);     // [16]
    signed char* sM = (signed char*)(sQM + 16); // [16][16]

    int n = blockIdx.x, tid = threadIdx.x;
    int i = tid >> 4, j = tid & 15;       // (i,j) position; also (jj,hh) for collab gemm
    int a0 = tid >> 5, ccol = tid & 31;   // rows a0, a0+8 for G'

    sM[tid] = g_M[n * 256 + tid];
    if (tid < 16) sNbr[tid] = nbrs[n * 16 + tid];
    for (int idx = tid; idx < 6144; idx += 256) sW[idx] = g_Wc2[idx];
    if (tid < 32) { sB[tid] = b2[tid]; sFCW[tid] = fcw[tid]; }
    __syncthreads();
    if (tid < 16) {
        unsigned qm = 0;
#pragma unroll
        for (int a = 0; a < 16; a++) {
            int p = sM[tid * 16 + a];
            if (p >= 0) qm |= 1u << p;
        }
        sQM[tid] = qm;
    }
    __syncthreads();

    issue_tile(0, tile0, tid, sNbr);

    float st[32];
#pragma unroll
    for (int c = 0; c < 32; c++) st[c] = 0.0f;
    ull y[16];
#pragma unroll
    for (int k = 0; k < 16; k++) y[k] = 0ull;
    float stb0 = 0.0f, stb1 = 0.0f;

    for (int t = 0; t < 16; t++) {
        float* buf = (t & 1) ? tile1 : tile0;
        if (t < 15) {
            issue_tile(t + 1, (t & 1) ? tile0 : tile1, tid, sNbr);
            asm volatile("cp.async.wait_group 1;");
        } else {
            asm volatile("cp.async.wait_group 0;");
        }
        __syncthreads();   // S1: tile t visible

        // phase A: G'[a][c] = valid(a) ? sum_{q in image} tile[m[a]*16+q][c] : 0
        {
            unsigned qm = sQM[t];
            int p0 = sM[t * 16 + a0], p1 = sM[t * 16 + a0 + 8];
            int r0 = (p0 < 0 ? 0 : p0) * 16, r1 = (p1 < 0 ? 0 : p1) * 16;
            float g0 = 0.0f, g1 = 0.0f;
#pragma unroll
            for (int q = 0; q < 16; q++) {
                if (qm & (1u << q)) {
                    g0 += tileElem(buf, r0 + q, ccol);
                    g1 += tileElem(buf, r1 + q, ccol);
                }
            }
            if (p0 < 0) g0 = 0.0f;
            if (p1 < 0) g1 = 0.0f;
            stb0 += g0; stb1 += g1;
            sGt[a0 * 33 + ccol] = g0;
            sGt[(a0 + 8) * 33 + ccol] = g1;
        }
        // st accumulation (per (i,j))
        {
            int pa = sM[t * 16 + i], pb = sM[t * 16 + j];
            if ((pa | pb) >= 0) {
                int r = pa * 16 + pb;
                const float4* tb = (const float4*)buf;
#pragma unroll
                for (int c4 = 0; c4 < 8; c4++) {
                    float4 v = tb[r * 8 + (c4 ^ (r & 7))];
                    st[c4 * 4 + 0] += v.x; st[c4 * 4 + 1] += v.y;
                    st[c4 * 4 + 2] += v.z; st[c4 * 4 + 3] += v.w;
                }
            }
        }
        __syncthreads();   // S2: G' ready

        // collaborative gb/dg gemm for row t: thread (jj=i, hh=j) computes h-pair
        {
            ull yb = 0ull;
            int pj = sM[t * 16 + i];
            if (pj >= 0) {
                int rd = pj * 17;
#pragma unroll
                for (int c = 0; c < 32; c++) {
                    float g = sGt[i * 33 + c];
                    float d = tileElem(buf, rd, c);
                    ull w0 = *(const ull*)&sW[0 * 1024 + c * 32 + 2 * j];
                    ull w5 = *(const ull*)&sW[5 * 1024 + c * 32 + 2 * j];
                    dfma(yb, pack2(g), w0);
                    dfma(yb, pack2(d), w5);
                }
            }
            ((ull*)sYB)[i * 17 + j] = yb;
        }
        // sum_ab[t][c] = sum_a G'[a][c]
        if (tid < 32) {
            float s = 0.0f;
#pragma unroll
            for (int a = 0; a < 16; a++) s += sGt[a * 33 + tid];
            sSAB[t * 32 + tid] = s;
        }
        __syncthreads();   // S3: sYB ready; all tile/G' reads done

        // pickup: threads with i == t fold their row of sYB into y
        if (i == t) {
            const ull* yb = (const ull*)sYB;
#pragma unroll
            for (int k = 0; k < 16; k++)
                y[k] = addx2(y[k], yb[j * 17 + k]);
        }
    }

    sSTB[a0 * 32 + ccol] = stb0;
    sSTB[(a0 + 8) * 32 + ccol] = stb1;
    __syncthreads();
    if (tid < 32) {
        float s = 0.0f;
#pragma unroll
        for (int t = 0; t < 16; t++) s += sSAB[t * 32 + tid];
        sSAL[tid] = s;
    }
    __syncthreads();
    {   // U[i][h]
        float ua = 0.0f, ub = 0.0f;
#pragma unroll
        for (int c = 0; c < 32; c++) {
            float w1b = sW[1 * 1024 + c * 32 + ccol];
            float w3b = sW[3 * 1024 + c * 32 + ccol];
            ua += sSAB[a0 * 32 + c] * w1b + sSTB[a0 * 32 + c] * w3b;
            ub += sSAB[(a0 + 8) * 32 + c] * w1b + sSTB[(a0 + 8) * 32 + c] * w3b;
        }
        sU[a0 * 32 + ccol] = ua;
        sU[(a0 + 8) * 32 + ccol] = ub;
    }
    if (tid < 32) {
        float s = 0.0f;
#pragma unroll
        for (int c = 0; c < 32; c++) s += sSAL[c] * sW[4 * 1024 + c * 32 + tid];
        sD[tid] = s;
    }
    __syncthreads();

    // st GEMM (W2b)
#pragma unroll
    for (int c = 0; c < 32; c++)
        gemm_row(y, pack2(st[c]), sW + 2 * 1024 + c * 32);

    // finish: add U/D/bias, relu, dot with fc weights, block-reduce
    float loc = 0.0f;
#pragma unroll
    for (int k = 0; k < 16; k++) {
        float lo, hi;
        unpack2(y[k], lo, hi);
        int h0 = 2 * k, h1 = 2 * k + 1;
        float v0 = lo + sU[i * 32 + h0] + sB[h0] + ((i == j) ? sD[h0] : 0.0f);
        float v1 = hi + sU[i * 32 + h1] + sB[h1] + ((i == j) ? sD[h1] : 0.0f);
        loc += fmaxf(v0, 0.0f) * sFCW[h0] + fmaxf(v1, 0.0f) * sFCW[h1];
    }
    sRED[tid] = loc;
    __syncthreads();
#pragma unroll
    for (int s = 128; s > 0; s >>= 1) {
        if (tid < s) sRED[tid] += sRED[tid + s];
        __syncthreads();
    }
    if (tid == 0) atomicAdd(&g_acc, sRED[0]);
}

__global__ void finish(const float* __restrict__ fcb, float* __restrict__ out) {
    out[0] = g_acc + fcb[0];
}

extern "C" void kernel_launch(void* const* d_in, const int* in_sizes, int n_in,
                              void* d_out, int out_size) {
    const float* X   = (const float*)d_in[0];
    const int*   nbr = (const int*)d_in[1];
    const float* W1  = (const float*)d_in[2];
    const float* b1  = (const float*)d_in[3];
    const float* W2  = (const float*)d_in[4];
    const float* b2  = (const float*)d_in[5];
    const float* fcw = (const float*)d_in[6];
    const float* fcb = (const float*)d_in[7];
    float* out = (float*)d_out;

    cudaFuncSetAttribute(layer2_kernel, cudaFuncAttributeMaxDynamicSharedMemorySize, SMEM2_BYTES);

    setup_kernel<<<258, 256>>>(nbr, W1, W2);
    layer1_kernel<<<NV, 256>>>(nbr, X, b1);
    layer2_kernel<<<NV, 256, SMEM2_BYTES>>>(nbr, b2, fcw);
    finish<<<1, 1>>>(fcb, out);
}

// round 4
// speedup vs baseline: 2.1306x; 1.0985x over previous
#include <cuda_runtime.h>

#define NV 256   // vertices
#define KD 16    // degree
#define HD 32    // hidden

// ---------------- globals (static init = 0; self-resetting across graph replays) ----------------
__device__ float g_F1[NV * 256 * HD];       // layer-1 output, 8 MB
__device__ unsigned g_flag[NV];             // per-vertex publish flag (epoch-stamped)
__device__ unsigned g_epoch;                // bumped by last block each call
__device__ unsigned g_done;                 // completion counter
__device__ float g_acc;                     // final scalar accumulator

typedef unsigned long long ull;

// ---------------- packed f32x2 helpers ----------------
__device__ __forceinline__ ull pack2(float x) {
    ull r; asm("mov.b64 %0, {%1, %1};" : "=l"(r) : "f"(x)); return r;
}
__device__ __forceinline__ ull pack2f(float lo, float hi) {
    ull r; asm("mov.b64 %0, {%1, %2};" : "=l"(r) : "f"(lo), "f"(hi)); return r;
}
__device__ __forceinline__ void unpack2(ull v, float& lo, float& hi) {
    asm("mov.b64 {%0, %1}, %2;" : "=f"(lo), "=f"(hi) : "l"(v));
}
__device__ __forceinline__ void dfma(ull& acc, ull a, ull b) {
    asm("fma.rn.f32x2 %0, %1, %2, %0;" : "+l"(acc) : "l"(a), "l"(b));
}
__device__ __forceinline__ ull addx2(ull a, ull b) {
    ull r; asm("add.rn.f32x2 %0, %1, %2;" : "=l"(r) : "l"(a), "l"(b)); return r;
}
__device__ __forceinline__ void gemm_row(ull* y, ull a, const float* wrow) {
    const longlong2* w = (const longlong2*)wrow;
#pragma unroll
    for (int k8 = 0; k8 < 8; k8++) {
        longlong2 v = w[k8];
        dfma(y[2 * k8 + 0], a, (ull)v.x);
        dfma(y[2 * k8 + 1], a, (ull)v.y);
    }
}
__device__ __forceinline__ void cp16(float* sdst, const float4* gsrc) {
    unsigned s = (unsigned)__cvta_generic_to_shared(sdst);
    asm volatile("cp.async.cg.shared.global [%0], [%1], 16;" :: "r"(s), "l"(gsrc));
}
__device__ __forceinline__ float tileElem(const float* buf, int r, int c) {
    return buf[r * 32 + (((c >> 2) ^ (r & 7)) << 2) + (c & 3)];
}

// ---------------- smem layout (floats) ----------------
#define OFF_W     0          // 6144 : Wc1 (first 3072) then Wc2
#define OFF_T0    6144       // 8192 : tile0 (layer1 scratch aliases here)
#define OFF_T1    14336      // 8192 : tile1
#define OFF_GT    22528      // 528
#define OFF_SAB   23056      // 512
#define OFF_STB   23568      // 512
#define OFF_SAL   24080      // 32
#define OFF_U     24112      // 512
#define OFF_D     24624      // 32
#define OFF_B2    24656      // 32
#define OFF_FCW   24688      // 32
#define OFF_RED   24720      // 256
#define OFF_YB    24976      // 1088 : double-buffered ull[2][16*17]
#define OFF_INT   26064      // small: nbr16,qm16,vm16,cnt16,misc4,M(64w)
#define SMEM_FLOATS (26064 + 16 + 16 + 16 + 16 + 4 + 64)
#define SMEM_BYTES  (SMEM_FLOATS * 4)

__device__ __forceinline__ void issue_tile(int t, float* buf, int tid, const int* sNbr) {
    const float4* src = (const float4*)(g_F1 + (size_t)sNbr[t] * 8192);
#pragma unroll
    for (int k = 0; k < 8; k++) {
        int g = k * 256 + tid;
        int r = g >> 3, c4 = g & 7;
        cp16(buf + r * 32 + ((c4 ^ (r & 7)) << 2), src + g);
    }
    asm volatile("cp.async.commit_group;");
}

__global__ __launch_bounds__(256, 2) void ccn_fused(const int* __restrict__ nbrs,
                                                    const float* __restrict__ X,
                                                    const float* __restrict__ W1,
                                                    const float* __restrict__ b1,
                                                    const float* __restrict__ W2,
                                                    const float* __restrict__ b2,
                                                    const float* __restrict__ fcw,
                                                    const float* __restrict__ fcb,
                                                    float* __restrict__ out) {
    extern __shared__ float smem[];
    float* sW    = smem + OFF_W;
    float* tile0 = smem + OFF_T0;
    float* tile1 = smem + OFF_T1;
    float* sGt   = smem + OFF_GT;    // [16][33]
    float* sSAB  = smem + OFF_SAB;   // [16][32]
    float* sSTB  = smem + OFF_STB;   // [16][32]
    float* sSAL  = smem + OFF_SAL;
    float* sU    = smem + OFF_U;
    float* sD    = smem + OFF_D;
    float* sB2   = smem + OFF_B2;
    float* sFCW  = smem + OFF_FCW;
    float* sRED  = smem + OFF_RED;
    ull*   sYB0  = (ull*)(smem + OFF_YB);        // [16*17]
    ull*   sYB1  = sYB0 + 272;
    int*      sNbr = (int*)(smem + OFF_INT);          // 16
    unsigned* sQM  = (unsigned*)(sNbr + 16);          // 16 image bitmask (bits p)
    unsigned* sVM  = (unsigned*)(sQM + 16);           // 16 validity bitmask (bits a)
    float*    sCnt = (float*)(sVM + 16);              // 16
    unsigned* sMisc = (unsigned*)(sCnt + 16);         // 4 (epoch)
    signed char* sM = (signed char*)(sMisc + 4);      // 256

    // layer-1 scratch aliases inside tile0
    float* sXn  = tile0;          // 256
    float* sAB1 = tile0 + 256;    // 256
    float* sTB1 = tile0 + 512;    // 256
    float* sAL1 = tile0 + 768;    // 16
    float* sU1  = tile0 + 784;    // 512
    float* sD1  = tile0 + 1296;   // 32
    float* sB1  = tile0 + 1328;   // 32

    int n = blockIdx.x, tid = threadIdx.x;
    int i = tid >> 4, j = tid & 15;
    int a0 = tid >> 5, ccol = tid & 31;

    // ============ stage 0: maps, neighbor features, Wc1, misc ============
    {
        int jv = nbrs[n * 16 + i];
        int target = nbrs[n * 16 + j];
        int r = -1;
#pragma unroll
        for (int p = 0; p < 16; p++)
            if (nbrs[jv * 16 + p] == target) r = p;
        sM[tid] = (signed char)r;                 // sM[t*16+a], t=i, a=j
        sXn[tid] = X[jv * 16 + j];                // row i = neighbor i, col j = channel
    }
    if (tid < 16) sNbr[tid] = nbrs[n * 16 + tid];
    // Wc1 (C=16): slot0=16*(W0+W6..W14)+W5, 1=W1, 2=16*W2, 3=W3, 4=W4, 5=W15
    for (int idx = tid; idx < 512; idx += 256) {
        int c = idx >> 5, h = idx & 31;
        float s = W1[(0 * 16 + c) * 32 + h];
#pragma unroll
        for (int m = 6; m < 15; m++) s += W1[(m * 16 + c) * 32 + h];
        sW[0 * 512 + c * 32 + h] = 16.0f * s + W1[(5 * 16 + c) * 32 + h];
        sW[1 * 512 + c * 32 + h] = W1[(1 * 16 + c) * 32 + h];
        sW[2 * 512 + c * 32 + h] = 16.0f * W1[(2 * 16 + c) * 32 + h];
        sW[3 * 512 + c * 32 + h] = W1[(3 * 16 + c) * 32 + h];
        sW[4 * 512 + c * 32 + h] = W1[(4 * 16 + c) * 32 + h];
        sW[5 * 512 + c * 32 + h] = W1[(15 * 16 + c) * 32 + h];
    }
    if (tid < HD) sB1[tid] = b1[tid];
    if (tid == 0) sMisc[0] = g_epoch;
    __syncthreads();
    if (tid < 16) {
        unsigned vm = 0, qm = 0;
#pragma unroll
        for (int a = 0; a < 16; a++) {
            int p = sM[tid * 16 + a];
            if (p >= 0) { vm |= 1u << a; qm |= 1u << p; }
        }
        sVM[tid] = vm;
        sQM[tid] = qm;
        sCnt[tid] = (float)__popc(vm);
    }
    __syncthreads();

    // ============ layer 1 (F0[n,p,q,c] = X[n,c] closed forms) ============
    sAB1[tid] = sCnt[i] * sCnt[i] * sXn[tid];
    {
        float s = 0.0f;
#pragma unroll
        for (int t = 0; t < 16; t++)
            if ((sVM[t] >> i) & 1) s += sCnt[t] * sXn[t * 16 + j];
        sTB1[tid] = s;
    }
    __syncthreads();
    if (tid < 16) {
        float s = 0.0f;
#pragma unroll
        for (int t = 0; t < 16; t++) s += sAB1[t * 16 + tid];
        sAL1[tid] = s;
    }
    __syncthreads();
    {
        int r0 = tid >> 5, h = tid & 31;
        float ua = 0.0f, ub = 0.0f;
#pragma unroll
        for (int c = 0; c < 16; c++) {
            float w1b = sW[1 * 512 + c * 32 + h];
            float w3b = sW[3 * 512 + c * 32 + h];
            ua += sAB1[r0 * 16 + c] * w1b + sTB1[r0 * 16 + c] * w3b;
            ub += sAB1[(r0 + 8) * 16 + c] * w1b + sTB1[(r0 + 8) * 16 + c] * w3b;
        }
        sU1[r0 * 32 + h] = ua;
        sU1[(r0 + 8) * 32 + h] = ub;
    }
    if (tid < HD) {
        float s = 0.0f;
#pragma unroll
        for (int c = 0; c < 16; c++) s += sAL1[c] * sW[4 * 512 + c * 32 + tid];
        sD1[tid] = s;
    }
    __syncthreads();
    {
        float st1[16];
#pragma unroll
        for (int c = 0; c < 16; c++) st1[c] = 0.0f;
#pragma unroll
        for (int t = 0; t < 16; t++) {
            unsigned vm = sVM[t];
            if (((vm >> i) & (vm >> j)) & 1) {
                const float4* xr = (const float4*)(sXn + t * 16);
#pragma unroll
                for (int c4 = 0; c4 < 4; c4++) {
                    float4 v = xr[c4];
                    st1[c4 * 4 + 0] += v.x; st1[c4 * 4 + 1] += v.y;
                    st1[c4 * 4 + 2] += v.z; st1[c4 * 4 + 3] += v.w;
                }
            }
        }
        ull y1[16];
#pragma unroll
        for (int k = 0; k < 16; k++) {
            int h0 = 2 * k, h1 = 2 * k + 1;
            float lo = sU1[i * 32 + h0] + sB1[h0] + ((i == j) ? sD1[h0] : 0.0f);
            float hi = sU1[i * 32 + h1] + sB1[h1] + ((i == j) ? sD1[h1] : 0.0f);
            y1[k] = pack2f(lo, hi);
        }
        bool val = (sM[tid] >= 0);
        float cnti = sCnt[i];
#pragma unroll
        for (int c = 0; c < 16; c++) {
            float xv = val ? sXn[i * 16 + c] : 0.0f;
            gemm_row(y1, pack2(st1[c]), sW + 2 * 512 + c * 32);
            gemm_row(y1, pack2(cnti * xv), sW + 0 * 512 + c * 32);
            gemm_row(y1, pack2(xv), sW + 5 * 512 + c * 32);
        }
        float* dst = g_F1 + (size_t)(n * 256 + tid) * 32;
#pragma unroll
        for (int q = 0; q < 8; q++) {
            float4 o;
            unpack2(y1[2 * q + 0], o.x, o.y);
            unpack2(y1[2 * q + 1], o.z, o.w);
            o.x = fmaxf(o.x, 0.0f); o.y = fmaxf(o.y, 0.0f);
            o.z = fmaxf(o.z, 0.0f); o.w = fmaxf(o.w, 0.0f);
            ((float4*)dst)[q] = o;
        }
    }
    __threadfence();
    __syncthreads();          // all F1[n] stores fenced; Wc1/layer1-smem reads done
    if (tid == 0) atomicExch(&g_flag[n], sMisc[0] + 1);   // publish

    // ============ Wc2 (C=32) — overlaps neighbors finishing layer 1 ============
    for (int idx = tid; idx < 1024; idx += 256) {
        int c = idx >> 5, h = idx & 31;
        float s = W2[(0 * 32 + c) * 32 + h];
#pragma unroll
        for (int m = 6; m < 15; m++) s += W2[(m * 32 + c) * 32 + h];
        sW[0 * 1024 + c * 32 + h] = 16.0f * s + W2[(5 * 32 + c) * 32 + h];
        sW[1 * 1024 + c * 32 + h] = W2[(1 * 32 + c) * 32 + h];
        sW[2 * 1024 + c * 32 + h] = 16.0f * W2[(2 * 32 + c) * 32 + h];
        sW[3 * 1024 + c * 32 + h] = W2[(3 * 32 + c) * 32 + h];
        sW[4 * 1024 + c * 32 + h] = W2[(4 * 32 + c) * 32 + h];
        sW[5 * 1024 + c * 32 + h] = W2[(15 * 32 + c) * 32 + h];
    }
    if (tid < 32) { sB2[tid] = b2[tid]; sFCW[tid] = fcw[tid]; }
    // acquire neighbors' flags
    if (tid < 16) {
        unsigned tgt = sMisc[0] + 1;
        const unsigned* fp = &g_flag[sNbr[tid]];
        unsigned v;
        do {
            asm volatile("ld.acquire.gpu.global.u32 %0, [%1];" : "=r"(v) : "l"(fp) : "memory");
        } while (v != tgt);
    }
    __syncthreads();

    // ============ layer 2 main loop ============
    issue_tile(0, tile0, tid, sNbr);

    float st[32];
#pragma unroll
    for (int c = 0; c < 32; c++) st[c] = 0.0f;
    ull y[16];
#pragma unroll
    for (int k = 0; k < 16; k++) y[k] = 0ull;
    float stb0 = 0.0f, stb1 = 0.0f;

    for (int t = 0; t < 16; t++) {
        float* buf = (t & 1) ? tile1 : tile0;
        asm volatile("cp.async.wait_group 0;");
        __syncthreads();                        // S1: tile t visible; iter t-1 fully done
        if (t < 15) issue_tile(t + 1, (t & 1) ? tile0 : tile1, tid, sNbr);

        // deferred pickup of iteration t-1's collaborative gemm
        if (t > 0 && i == t - 1) {
            const ull* yb = ((t - 1) & 1) ? sYB1 : sYB0;
#pragma unroll
            for (int k = 0; k < 16; k++)
                y[k] = addx2(y[k], yb[j * 17 + k]);
        }

        // phase A: G'[a][c] (a-indexed, validity-masked) + stb accumulation
        {
            unsigned qm = sQM[t];
            int p0 = sM[t * 16 + a0], p1 = sM[t * 16 + a0 + 8];
            int r0 = (p0 < 0 ? 0 : p0) * 16, r1 = (p1 < 0 ? 0 : p1) * 16;
            float g0 = 0.0f, g1 = 0.0f;
#pragma unroll
            for (int q = 0; q < 16; q++) {
                if (qm & (1u << q)) {
                    g0 += tileElem(buf, r0 + q, ccol);
                    g1 += tileElem(buf, r1 + q, ccol);
                }
            }
            if (p0 < 0) g0 = 0.0f;
            if (p1 < 0) g1 = 0.0f;
            stb0 += g0; stb1 += g1;
            sGt[a0 * 33 + ccol] = g0;
            sGt[(a0 + 8) * 33 + ccol] = g1;
        }
        // st accumulation (per (i,j))
        {
            int pa = sM[t * 16 + i], pb = sM[t * 16 + j];
            if ((pa | pb) >= 0) {
                int r = pa * 16 + pb;
                const float4* tb = (const float4*)buf;
#pragma unroll
                for (int c4 = 0; c4 < 8; c4++) {
                    float4 v = tb[r * 8 + (c4 ^ (r & 7))];
                    st[c4 * 4 + 0] += v.x; st[c4 * 4 + 1] += v.y;
                    st[c4 * 4 + 2] += v.z; st[c4 * 4 + 3] += v.w;
                }
            }
        }
        __syncthreads();                        // S2: G' ready

        // collaborative gb/dg gemm for row t → sYB[t&1]
        {
            ull yb = 0ull;
            int pj = sM[t * 16 + i];
            if (pj >= 0) {
                int rd = pj * 17;
#pragma unroll
                for (int c = 0; c < 32; c++) {
                    float g = sGt[i * 33 + c];
                    float d = tileElem(buf, rd, c);
                    ull w0 = *(const ull*)&sW[0 * 1024 + c * 32 + 2 * j];
                    ull w5 = *(const ull*)&sW[5 * 1024 + c * 32 + 2 * j];
                    dfma(yb, pack2(g), w0);
                    dfma(yb, pack2(d), w5);
                }
            }
            ull* out_yb = (t & 1) ? sYB1 : sYB0;
            out_yb[i * 17 + j] = yb;
        }
        if (tid < 32) {
            float s = 0.0f;
#pragma unroll
            for (int a = 0; a < 16; a++) s += sGt[a * 33 + tid];
            sSAB[t * 32 + tid] = s;
        }
    }

    sSTB[a0 * 32 + ccol] = stb0;
    sSTB[(a0 + 8) * 32 + ccol] = stb1;
    __syncthreads();                            // also orders sYB1 (iter 15) writes
    if (i == 15) {                              // final pickup
#pragma unroll
        for (int k = 0; k < 16; k++)
            y[k] = addx2(y[k], sYB1[j * 17 + k]);
    }
    if (tid < 32) {
        float s = 0.0f;
#pragma unroll
        for (int t = 0; t < 16; t++) s += sSAB[t * 32 + tid];
        sSAL[tid] = s;
    }
    __syncthreads();
    {   // U[i][h]
        float ua = 0.0f, ub = 0.0f;
#pragma unroll
        for (int c = 0; c < 32; c++) {
            float w1b = sW[1 * 1024 + c * 32 + ccol];
            float w3b = sW[3 * 1024 + c * 32 + ccol];
            ua += sSAB[a0 * 32 + c] * w1b + sSTB[a0 * 32 + c] * w3b;
            ub += sSAB[(a0 + 8) * 32 + c] * w1b + sSTB[(a0 + 8) * 32 + c] * w3b;
        }
        sU[a0 * 32 + ccol] = ua;
        sU[(a0 + 8) * 32 + ccol] = ub;
    }
    if (tid < 32) {
        float s = 0.0f;
#pragma unroll
        for (int c = 0; c < 32; c++) s += sSAL[c] * sW[4 * 1024 + c * 32 + tid];
        sD[tid] = s;
    }
    __syncthreads();

    // st GEMM (W2b)
#pragma unroll
    for (int c = 0; c < 32; c++)
        gemm_row(y, pack2(st[c]), sW + 2 * 1024 + c * 32);

    // finish: add U/D/bias, relu, dot fc, block-reduce
    float loc = 0.0f;
#pragma unroll
    for (int k = 0; k < 16; k++) {
        float lo, hi;
        unpack2(y[k], lo, hi);
        int h0 = 2 * k, h1 = 2 * k + 1;
        float v0 = lo + sU[i * 32 + h0] + sB2[h0] + ((i == j) ? sD[h0] : 0.0f);
        float v1 = hi + sU[i * 32 + h1] + sB2[h1] + ((i == j) ? sD[h1] : 0.0f);
        loc += fmaxf(v0, 0.0f) * sFCW[h0] + fmaxf(v1, 0.0f) * sFCW[h1];
    }
    sRED[tid] = loc;
    __syncthreads();
#pragma unroll
    for (int s = 128; s > 0; s >>= 1) {
        if (tid < s) sRED[tid] += sRED[tid + s];
        __syncthreads();
    }
    if (tid == 0) {
        atomicAdd(&g_acc, sRED[0]);
        __threadfence();
        unsigned prev = atomicAdd(&g_done, 1);
        if (prev == NV - 1) {                  // last block: finalize + reset
            float tot = atomicAdd(&g_acc, 0.0f);
            out[0] = tot + fcb[0];
            g_acc = 0.0f;
            g_done = 0;
            g_epoch = sMisc[0] + 1;
            __threadfence();
        }
    }
}

extern "C" void kernel_launch(void* const* d_in, const int* in_sizes, int n_in,
                              void* d_out, int out_size) {
    const float* X   = (const float*)d_in[0];
    const int*   nbr = (const int*)d_in[1];
    const float* W1  = (const float*)d_in[2];
    const float* b1  = (const float*)d_in[3];
    const float* W2  = (const float*)d_in[4];
    const float* b2  = (const float*)d_in[5];
    const float* fcw = (const float*)d_in[6];
    const float* fcb = (const float*)d_in[7];
    float* out = (float*)d_out;

    cudaFuncSetAttribute(ccn_fused, cudaFuncAttributeMaxDynamicSharedMemorySize, SMEM_BYTES);
    ccn_fused<<<NV, 256, SMEM_BYTES>>>(nbr, X, W1, b1, W2, b2, fcw, fcb, out);
}

// round 5
// speedup vs baseline: 2.1395x; 1.0042x over previous
#include <cuda_runtime.h>

#define NV 256   // vertices
#define KD 16    // degree
#define HD 32    // hidden

// ---------------- globals (static init = 0; self-resetting across graph replays) ----------------
__device__ float g_F1[NV * 256 * HD];       // layer-1 output, 8 MB
__device__ unsigned g_flag[NV];             // per-vertex publish flag (epoch-stamped)
__device__ unsigned g_epoch;                // bumped by last block each call
__device__ unsigned g_done;                 // completion counter
__device__ float g_acc;                     // final scalar accumulator

typedef unsigned long long ull;

// ---------------- packed f32x2 helpers ----------------
__device__ __forceinline__ ull pack2(float x) {
    ull r; asm("mov.b64 %0, {%1, %1};" : "=l"(r) : "f"(x)); return r;
}
__device__ __forceinline__ ull pack2f(float lo, float hi) {
    ull r; asm("mov.b64 %0, {%1, %2};" : "=l"(r) : "f"(lo), "f"(hi)); return r;
}
__device__ __forceinline__ void unpack2(ull v, float& lo, float& hi) {
    asm("mov.b64 {%0, %1}, %2;" : "=f"(lo), "=f"(hi) : "l"(v));
}
__device__ __forceinline__ void dfma(ull& acc, ull a, ull b) {
    asm("fma.rn.f32x2 %0, %1, %2, %0;" : "+l"(acc) : "l"(a), "l"(b));
}
__device__ __forceinline__ ull addx2(ull a, ull b) {
    ull r; asm("add.rn.f32x2 %0, %1, %2;" : "=l"(r) : "l"(a), "l"(b)); return r;
}
__device__ __forceinline__ void gemm_row(ull* y, ull a, const float* wrow) {
    const longlong2* w = (const longlong2*)wrow;
#pragma unroll
    for (int k8 = 0; k8 < 8; k8++) {
        longlong2 v = w[k8];
        dfma(y[2 * k8 + 0], a, (ull)v.x);
        dfma(y[2 * k8 + 1], a, (ull)v.y);
    }
}
__device__ __forceinline__ void cp16(float* sdst, const float4* gsrc) {
    unsigned s = (unsigned)__cvta_generic_to_shared(sdst);
    asm volatile("cp.async.cg.shared.global [%0], [%1], 16;" :: "r"(s), "l"(gsrc));
}

// ---------------- smem layout (floats) ----------------
#define OFF_W     0          // 6144 : Wc1 (first 3072) then Wc2 [6][32][32]
#define OFF_T0    6144       // 8192 : tile0 (layer1 scratch aliases here)
#define OFF_T1    14336      // 8192 : tile1
#define OFF_GT    22528      // 1152 : sGt double-buffer [2][16][36]
#define OFF_DG    23680      // 1152 : sDiag double-buffer [2][16][36]
#define OFF_SAB   24832      // 512
#define OFF_STB   25344      // 512
#define OFF_SAL   25856      // 32
#define OFF_U     25888      // 512
#define OFF_D     26400      // 32
#define OFF_B2    26432      // 32
#define OFF_FCW   26464      // 32
#define OFF_RED   26496      // 32 (warp partials)
#define OFF_YB    26528      // 1088 : double-buffered ull[2][16*17]
#define OFF_INT   27616      // nbr16,qm16,vm16,cnt16,misc4,M(64w)
#define SMEM_FLOATS (27616 + 16 + 16 + 16 + 16 + 4 + 64)
#define SMEM_BYTES  (SMEM_FLOATS * 4)

__device__ __forceinline__ void issue_tile(int t, float* buf, int tid, const int* sNbr) {
    const float4* src = (const float4*)(g_F1 + (size_t)sNbr[t] * 8192);
#pragma unroll
    for (int k = 0; k < 8; k++) {
        int g = k * 256 + tid;
        int r = g >> 3, c4 = g & 7;
        cp16(buf + r * 32 + ((c4 ^ (r & 7)) << 2), src + g);
    }
    asm volatile("cp.async.commit_group;");
}

// collaborative gb/dg gemm for tile row tp: thread (i,j) computes h-pair (2j,2j+1) of output row i
__device__ __forceinline__ void collab_row(int tp, const float* sGtBuf, const float* sDgBuf,
                                           ull* sYBBuf, const float* sW,
                                           const signed char* sM, int i, int j) {
    int pj = sM[tp * 16 + i];
    ull yb0 = 0, yb1 = 0, yb2 = 0, yb3 = 0;
    if (pj >= 0) {
        const longlong2* gr = (const longlong2*)(sGtBuf + i * 36);
        const longlong2* dr = (const longlong2*)(sDgBuf + i * 36);
        const float* w0b = sW + 0 * 1024 + 2 * j;
        const float* w5b = sW + 5 * 1024 + 2 * j;
#pragma unroll
        for (int c4 = 0; c4 < 8; c4++) {
            longlong2 g2 = gr[c4];
            longlong2 d2 = dr[c4];
            float ga, gb_, gc_, gd_, da, db, dc_, dd_;
            unpack2((ull)g2.x, ga, gb_); unpack2((ull)g2.y, gc_, gd_);
            unpack2((ull)d2.x, da, db); unpack2((ull)d2.y, dc_, dd_);
            int c = c4 * 4;
            dfma(yb0, pack2(ga),  *(const ull*)(w0b + (c + 0) * 32));
            dfma(yb2, pack2(da),  *(const ull*)(w5b + (c + 0) * 32));
            dfma(yb1, pack2(gb_), *(const ull*)(w0b + (c + 1) * 32));
            dfma(yb3, pack2(db),  *(const ull*)(w5b + (c + 1) * 32));
            dfma(yb0, pack2(gc_), *(const ull*)(w0b + (c + 2) * 32));
            dfma(yb2, pack2(dc_), *(const ull*)(w5b + (c + 2) * 32));
            dfma(yb1, pack2(gd_), *(const ull*)(w0b + (c + 3) * 32));
            dfma(yb3, pack2(dd_), *(const ull*)(w5b + (c + 3) * 32));
        }
    }
    sYBBuf[i * 17 + j] = addx2(addx2(yb0, yb1), addx2(yb2, yb3));
}

__global__ __launch_bounds__(256, 2) void ccn_fused(const int* __restrict__ nbrs,
                                                    const float* __restrict__ X,
                                                    const float* __restrict__ W1,
                                                    const float* __restrict__ b1,
                                                    const float* __restrict__ W2,
                                                    const float* __restrict__ b2,
                                                    const float* __restrict__ fcw,
                                                    const float* __restrict__ fcb,
                                                    float* __restrict__ out) {
    extern __shared__ float smem[];
    float* sW    = smem + OFF_W;
    float* tile0 = smem + OFF_T0;
    float* tile1 = smem + OFF_T1;
    float* sGt   = smem + OFF_GT;    // [2][16][36]
    float* sDg   = smem + OFF_DG;    // [2][16][36]
    float* sSAB  = smem + OFF_SAB;   // [16][32]
    float* sSTB  = smem + OFF_STB;   // [16][32]
    float* sSAL  = smem + OFF_SAL;
    float* sU    = smem + OFF_U;
    float* sD    = smem + OFF_D;
    float* sB2   = smem + OFF_B2;
    float* sFCW  = smem + OFF_FCW;
    float* sRED  = smem + OFF_RED;   // 32 warp partials
    ull*   sYB   = (ull*)(smem + OFF_YB);        // [2][16*17]
    int*      sNbr = (int*)(smem + OFF_INT);          // 16
    unsigned* sQM  = (unsigned*)(sNbr + 16);          // 16 image bitmask (bits p/q)
    unsigned* sVM  = (unsigned*)(sQM + 16);           // 16 validity bitmask (bits a)
    float*    sCnt = (float*)(sVM + 16);              // 16
    unsigned* sMisc = (unsigned*)(sCnt + 16);         // 4 (epoch)
    signed char* sM = (signed char*)(sMisc + 4);      // 256

    // layer-1 scratch aliases inside tile0
    float* sXn  = tile0;          // 256
    float* sAB1 = tile0 + 256;    // 256
    float* sTB1 = tile0 + 512;    // 256
    float* sAL1 = tile0 + 768;    // 16
    float* sU1  = tile0 + 784;    // 512
    float* sD1  = tile0 + 1296;   // 32
    float* sB1  = tile0 + 1328;   // 32

    int n = blockIdx.x, tid = threadIdx.x;
    int i = tid >> 4, j = tid & 15;

    // ============ stage 0: maps, neighbor features, Wc1, misc ============
    {
        int jv = nbrs[n * 16 + i];
        int target = nbrs[n * 16 + j];
        int r = -1;
#pragma unroll
        for (int p = 0; p < 16; p++)
            if (nbrs[jv * 16 + p] == target) r = p;
        sM[tid] = (signed char)r;                 // sM[t*16+a], t=i, a=j
        sXn[tid] = X[jv * 16 + j];
    }
    if (tid < 16) sNbr[tid] = nbrs[n * 16 + tid];
    // Wc1 (C=16): slot0=16*(W0+W6..14)+W5, 1=W1, 2=16*W2, 3=W3, 4=W4, 5=W15
    for (int idx = tid; idx < 512; idx += 256) {
        int c = idx >> 5, h = idx & 31;
        float s = W1[(0 * 16 + c) * 32 + h];
#pragma unroll
        for (int m = 6; m < 15; m++) s += W1[(m * 16 + c) * 32 + h];
        sW[0 * 512 + c * 32 + h] = 16.0f * s + W1[(5 * 16 + c) * 32 + h];
        sW[1 * 512 + c * 32 + h] = W1[(1 * 16 + c) * 32 + h];
        sW[2 * 512 + c * 32 + h] = 16.0f * W1[(2 * 16 + c) * 32 + h];
        sW[3 * 512 + c * 32 + h] = W1[(3 * 16 + c) * 32 + h];
        sW[4 * 512 + c * 32 + h] = W1[(4 * 16 + c) * 32 + h];
        sW[5 * 512 + c * 32 + h] = W1[(15 * 16 + c) * 32 + h];
    }
    if (tid < HD) sB1[tid] = b1[tid];
    if (tid == 0) sMisc[0] = g_epoch;
    __syncthreads();
    if (tid < 16) {
        unsigned vm = 0, qm = 0;
#pragma unroll
        for (int a = 0; a < 16; a++) {
            int p = sM[tid * 16 + a];
            if (p >= 0) { vm |= 1u << a; qm |= 1u << p; }
        }
        sVM[tid] = vm;
        sQM[tid] = qm;
        sCnt[tid] = (float)__popc(vm);
    }
    __syncthreads();

    // ============ layer 1 (F0[n,p,q,c] = X[n,c] closed forms) ============
    sAB1[tid] = sCnt[i] * sCnt[i] * sXn[tid];
    {
        float s = 0.0f;
#pragma unroll
        for (int t = 0; t < 16; t++)
            if ((sVM[t] >> i) & 1) s += sCnt[t] * sXn[t * 16 + j];
        sTB1[tid] = s;
    }
    __syncthreads();
    if (tid < 16) {
        float s = 0.0f;
#pragma unroll
        for (int t = 0; t < 16; t++) s += sAB1[t * 16 + tid];
        sAL1[tid] = s;
    }
    __syncthreads();
    {
        int r0 = tid >> 5, h = tid & 31;
        float ua = 0.0f, ub = 0.0f;
#pragma unroll
        for (int c = 0; c < 16; c++) {
            float w1b = sW[1 * 512 + c * 32 + h];
            float w3b = sW[3 * 512 + c * 32 + h];
            ua += sAB1[r0 * 16 + c] * w1b + sTB1[r0 * 16 + c] * w3b;
            ub += sAB1[(r0 + 8) * 16 + c] * w1b + sTB1[(r0 + 8) * 16 + c] * w3b;
        }
        sU1[r0 * 32 + h] = ua;
        sU1[(r0 + 8) * 32 + h] = ub;
    }
    if (tid < HD) {
        float s = 0.0f;
#pragma unroll
        for (int c = 0; c < 16; c++) s += sAL1[c] * sW[4 * 512 + c * 32 + tid];
        sD1[tid] = s;
    }
    __syncthreads();
    {
        float st1[16];
#pragma unroll
        for (int c = 0; c < 16; c++) st1[c] = 0.0f;
#pragma unroll
        for (int t = 0; t < 16; t++) {
            unsigned vm = sVM[t];
            if (((vm >> i) & (vm >> j)) & 1) {
                const float4* xr = (const float4*)(sXn + t * 16);
#pragma unroll
                for (int c4 = 0; c4 < 4; c4++) {
                    float4 v = xr[c4];
                    st1[c4 * 4 + 0] += v.x; st1[c4 * 4 + 1] += v.y;
                    st1[c4 * 4 + 2] += v.z; st1[c4 * 4 + 3] += v.w;
                }
            }
        }
        ull y1[16];
#pragma unroll
        for (int k = 0; k < 16; k++) {
            int h0 = 2 * k, h1 = 2 * k + 1;
            float lo = sU1[i * 32 + h0] + sB1[h0] + ((i == j) ? sD1[h0] : 0.0f);
            float hi = sU1[i * 32 + h1] + sB1[h1] + ((i == j) ? sD1[h1] : 0.0f);
            y1[k] = pack2f(lo, hi);
        }
        bool val = (sM[tid] >= 0);
        float cnti = sCnt[i];
#pragma unroll
        for (int c = 0; c < 16; c++) {
            float xv = val ? sXn[i * 16 + c] : 0.0f;
            gemm_row(y1, pack2(st1[c]), sW + 2 * 512 + c * 32);
            gemm_row(y1, pack2(cnti * xv), sW + 0 * 512 + c * 32);
            gemm_row(y1, pack2(xv), sW + 5 * 512 + c * 32);
        }
        float* dst = g_F1 + (size_t)(n * 256 + tid) * 32;
#pragma unroll
        for (int q = 0; q < 8; q++) {
            float4 o;
            unpack2(y1[2 * q + 0], o.x, o.y);
            unpack2(y1[2 * q + 1], o.z, o.w);
            o.x = fmaxf(o.x, 0.0f); o.y = fmaxf(o.y, 0.0f);
            o.z = fmaxf(o.z, 0.0f); o.w = fmaxf(o.w, 0.0f);
            ((float4*)dst)[q] = o;
        }
    }
    __threadfence();
    __syncthreads();
    if (tid == 0) atomicExch(&g_flag[n], sMisc[0] + 1);   // publish

    // ============ Wc2 (C=32) — overlaps neighbors finishing layer 1 ============
    for (int idx = tid; idx < 1024; idx += 256) {
        int c = idx >> 5, h = idx & 31;
        float s = W2[(0 * 32 + c) * 32 + h];
#pragma unroll
        for (int m = 6; m < 15; m++) s += W2[(m * 32 + c) * 32 + h];
        sW[0 * 1024 + c * 32 + h] = 16.0f * s + W2[(5 * 32 + c) * 32 + h];
        sW[1 * 1024 + c * 32 + h] = W2[(1 * 32 + c) * 32 + h];
        sW[2 * 1024 + c * 32 + h] = 16.0f * W2[(2 * 32 + c) * 32 + h];
        sW[3 * 1024 + c * 32 + h] = W2[(3 * 32 + c) * 32 + h];
        sW[4 * 1024 + c * 32 + h] = W2[(4 * 32 + c) * 32 + h];
        sW[5 * 1024 + c * 32 + h] = W2[(15 * 32 + c) * 32 + h];
    }
    if (tid < 32) { sB2[tid] = b2[tid]; sFCW[tid] = fcw[tid]; }
    // acquire neighbors' flags
    if (tid < 16) {
        unsigned tgt = sMisc[0] + 1;
        const unsigned* fp = &g_flag[sNbr[tid]];
        unsigned v;
        do {
            asm volatile("ld.acquire.gpu.global.u32 %0, [%1];" : "=r"(v) : "l"(fp) : "memory");
        } while (v != tgt);
    }
    __syncthreads();

    // ============ layer 2 main loop (single barrier per iteration, SW-pipelined) ============
    issue_tile(0, tile0, tid, sNbr);

    int aA = tid >> 4;            // phase-A row (same as i)
    int half = (tid >> 3) & 1;    // q-half
    int c4A = tid & 7;            // float4 column

    ull st2[16];
#pragma unroll
    for (int c = 0; c < 16; c++) st2[c] = 0ull;
    ull y[16];
#pragma unroll
    for (int k = 0; k < 16; k++) y[k] = 0ull;
    ull stbA = 0ull, stbB = 0ull;

    for (int t = 0; t < 16; t++) {
        float* buf = (t & 1) ? tile1 : tile0;
        const float4* bufv = (const float4*)buf;
        asm volatile("cp.async.wait_group 0;");
        __syncthreads();   // tile t ready; iter t-1 writes (sGt/sDg[t-1], sYB[t-2]) visible
        if (t < 15) issue_tile(t + 1, (t & 1) ? tile0 : tile1, tid, sNbr);

        // deferred pickup of collab(t-2)
        if (t >= 2 && i == t - 2) {
            const ull* yb = sYB + (t & 1) * 272;
#pragma unroll
            for (int k = 0; k < 16; k++)
                y[k] = addx2(y[k], yb[j * 17 + k]);
        }

        // ---- phase A on tile t: G'[a] rows + diag rows + stb accumulation
        {
            unsigned qm = sQM[t];
            int pA = sM[t * 16 + aA];
            int rbase = (pA < 0 ? 0 : pA) * 16 + half * 8;
            ull acc0 = 0ull, acc1 = 0ull;
#pragma unroll
            for (int k = 0; k < 8; k++) {
                if (qm & (1u << (half * 8 + k))) {
                    int r = rbase + k;
                    longlong2 v = *(const longlong2*)(bufv + r * 8 + (c4A ^ (r & 7)));
                    acc0 = addx2(acc0, (ull)v.x);
                    acc1 = addx2(acc1, (ull)v.y);
                }
            }
            if (pA < 0) { acc0 = 0ull; acc1 = 0ull; }
            float f0, f1, f2, f3;
            unpack2(acc0, f0, f1);
            unpack2(acc1, f2, f3);
            f0 += __shfl_xor_sync(0xffffffffu, f0, 8);
            f1 += __shfl_xor_sync(0xffffffffu, f1, 8);
            f2 += __shfl_xor_sync(0xffffffffu, f2, 8);
            f3 += __shfl_xor_sync(0xffffffffu, f3, 8);
            stbA = addx2(stbA, pack2f(f0, f1));
            stbB = addx2(stbB, pack2f(f2, f3));
            float* gbuf = sGt + (t & 1) * 576;
            if (half == 0) {
                float4 o; o.x = f0; o.y = f1; o.z = f2; o.w = f3;
                *(float4*)(gbuf + aA * 36 + c4A * 4) = o;
            } else {
                int rd = (pA < 0 ? 0 : pA) * 17;
                longlong2 dv = *(const longlong2*)(bufv + rd * 8 + (c4A ^ (rd & 7)));
                *(longlong2*)(sDg + (t & 1) * 576 + aA * 36 + c4A * 4) = dv;
            }
        }
        // ---- st accumulation (per (i,j))
        {
            int pa = sM[t * 16 + i], pb = sM[t * 16 + j];
            if ((pa | pb) >= 0) {
                int r = pa * 16 + pb;
#pragma unroll
                for (int c4 = 0; c4 < 8; c4++) {
                    longlong2 v = *(const longlong2*)(bufv + r * 8 + (c4 ^ (r & 7)));
                    st2[2 * c4 + 0] = addx2(st2[2 * c4 + 0], (ull)v.x);
                    st2[2 * c4 + 1] = addx2(st2[2 * c4 + 1], (ull)v.y);
                }
            }
        }
        // ---- collab gemm + sum_ab for tile t-1 (reads previous buffers)
        if (t >= 1) {
            int pb = (t - 1) & 1;
            collab_row(t - 1, sGt + pb * 576, sDg + pb * 576, sYB + pb * 272, sW, sM, i, j);
            if (tid < 32) {
                const float* gp = sGt + pb * 576;
                float s = 0.0f;
#pragma unroll
                for (int a = 0; a < 16; a++) s += gp[a * 36 + tid];
                sSAB[(t - 1) * 32 + tid] = s;
            }
        }
    }

    // ---- epilogue of the pipeline
    __syncthreads();   // phase A(15) + collab(14) visible
    if (i == 14) {
        const ull* yb = sYB + 0 * 272;   // (14)&1 = 0
#pragma unroll
        for (int k = 0; k < 16; k++)
            y[k] = addx2(y[k], yb[j * 17 + k]);
    }
    collab_row(15, sGt + 576, sDg + 576, sYB + 272, sW, sM, i, j);
    if (tid < 32) {
        const float* gp = sGt + 576;
        float s = 0.0f;
#pragma unroll
        for (int a = 0; a < 16; a++) s += gp[a * 36 + tid];
        sSAB[15 * 32 + tid] = s;
    }
    if (half == 0) {   // write sum_tb (accumulated over all t)
        float4 o;
        unpack2(stbA, o.x, o.y);
        unpack2(stbB, o.z, o.w);
        *(float4*)(sSTB + aA * 32 + c4A * 4) = o;
    }
    __syncthreads();
    if (i == 15) {
        const ull* yb = sYB + 272;
#pragma unroll
        for (int k = 0; k < 16; k++)
            y[k] = addx2(y[k], yb[j * 17 + k]);
    }
    if (tid < 32) {
        float s = 0.0f;
#pragma unroll
        for (int t = 0; t < 16; t++) s += sSAB[t * 32 + tid];
        sSAL[tid] = s;
    }
    __syncthreads();
    {   // U[i][h]
        int a0 = tid >> 5, ccol = tid & 31;
        float ua = 0.0f, ub = 0.0f;
#pragma unroll
        for (int c = 0; c < 32; c++) {
            float w1b = sW[1 * 1024 + c * 32 + ccol];
            float w3b = sW[3 * 1024 + c * 32 + ccol];
            ua += sSAB[a0 * 32 + c] * w1b + sSTB[a0 * 32 + c] * w3b;
            ub += sSAB[(a0 + 8) * 32 + c] * w1b + sSTB[(a0 + 8) * 32 + c] * w3b;
        }
        sU[a0 * 32 + ccol] = ua;
        sU[(a0 + 8) * 32 + ccol] = ub;
    }
    if (tid < 32) {
        float s = 0.0f;
#pragma unroll
        for (int c = 0; c < 32; c++) s += sSAL[c] * sW[4 * 1024 + c * 32 + tid];
        sD[tid] = s;
    }
    __syncthreads();

    // ---- st GEMM (W2b)
#pragma unroll
    for (int cc = 0; cc < 16; cc++) {
        float lo, hi;
        unpack2(st2[cc], lo, hi);
        gemm_row(y, pack2(lo), sW + 2 * 1024 + (2 * cc + 0) * 32);
        gemm_row(y, pack2(hi), sW + 2 * 1024 + (2 * cc + 1) * 32);
    }

    // ---- finish: add U/D/bias, relu, dot fc, reduce
    float loc = 0.0f;
#pragma unroll
    for (int k = 0; k < 16; k++) {
        float lo, hi;
        unpack2(y[k], lo, hi);
        int h0 = 2 * k, h1 = 2 * k + 1;
        float v0 = lo + sU[i * 32 + h0] + sB2[h0] + ((i == j) ? sD[h0] : 0.0f);
        float v1 = hi + sU[i * 32 + h1] + sB2[h1] + ((i == j) ? sD[h1] : 0.0f);
        loc += fmaxf(v0, 0.0f) * sFCW[h0] + fmaxf(v1, 0.0f) * sFCW[h1];
    }
#pragma unroll
    for (int o = 16; o > 0; o >>= 1) loc += __shfl_xor_sync(0xffffffffu, loc, o);
    if ((tid & 31) == 0) sRED[tid >> 5] = loc;
    __syncthreads();
    if (tid == 0) {
        float s = 0.0f;
#pragma unroll
        for (int w = 0; w < 8; w++) s += sRED[w];
        atomicAdd(&g_acc, s);
        __threadfence();
        unsigned prev = atomicAdd(&g_done, 1);
        if (prev == NV - 1) {                  // last block: finalize + reset
            float tot = atomicAdd(&g_acc, 0.0f);
            out[0] = tot + fcb[0];
            g_acc = 0.0f;
            g_done = 0;
            g_epoch = sMisc[0] + 1;
            __threadfence();
        }
    }
}

extern "C" void kernel_launch(void* const* d_in, const int* in_sizes, int n_in,
                              void* d_out, int out_size) {
    const float* X   = (const float*)d_in[0];
    const int*   nbr = (const int*)d_in[1];
    const float* W1  = (const float*)d_in[2];
    const float* b1  = (const float*)d_in[3];
    const float* W2  = (const float*)d_in[4];
    const float* b2  = (const float*)d_in[5];
    const float* fcw = (const float*)d_in[6];
    const float* fcb = (const float*)d_in[7];
    float* out = (float*)d_out;

    cudaFuncSetAttribute(ccn_fused, cudaFuncAttributeMaxDynamicSharedMemorySize, SMEM_BYTES);
    ccn_fused<<<NV, 256, SMEM_BYTES>>>(nbr, X, W1, b1, W2, b2, fcw, fcb, out);
}